// round 2
// baseline (speedup 1.0000x reference)
#include <cuda_runtime.h>
#include <math.h>

#define B_ 64
#define T_ 256
#define F_ 64
#define U_ 512
#define G_ 2048            // 4*U
#define TB_ (T_*B_)        // 16384
#define NCTA 128

// ---------------- device scratch (static globals: no allocs allowed) ----------------
__device__ float g_xc[(size_t)TB_ * G_];      // x-contrib + bias for current layer  [t][b][4U]
__device__ float g_hseq[(size_t)TB_ * U_];    // h sequence of current layer         [t][b][U]
__device__ float g_hbuf[2][B_ * U_];          // ping-pong recurrent h
__device__ float g_cst_s[2][B_ * U_];         // saved final c (enc L0, enc L1)
__device__ float g_hst_s[2][B_ * U_];         // saved final h (enc L0, enc L1)
__device__ unsigned g_gen;
__device__ unsigned g_cnt;

// ---------------- grid-wide barrier (all NCTA CTAs co-resident, 1 CTA/SM) ----------------
__device__ __forceinline__ void grid_bar() {
    __syncthreads();
    if (threadIdx.x == 0) {
        __threadfence();                                   // release my writes
        unsigned my = *(volatile unsigned*)&g_gen;
        unsigned a = atomicAdd(&g_cnt, 1u);
        if (a == NCTA - 1u) {
            g_cnt = 0u;
            __threadfence();
            atomicExch(&g_gen, my + 1u);                   // release
        } else {
            // backoff spin: don't hammer the L2 line from 127 CTAs
            while (*(volatile unsigned*)&g_gen == my) {
                __nanosleep(40);
            }
        }
        __threadfence();                                   // acquire others' writes
    }
    __syncthreads();
}

__device__ __forceinline__ float sigf(float x) { return 1.f / (1.f + __expf(-x)); }

// ---------------- init working h buffer: sel 0 = zeros, 1 = enc L0 final h, 2 = enc L1 final h
__global__ void set_h(int sel) {
    int i = blockIdx.x * blockDim.x + threadIdx.x;
    if (i < B_ * U_) {
        float v = 0.f;
        if (sel == 1) v = g_hst_s[0][i];
        else if (sel == 2) v = g_hst_s[1][i];
        g_hbuf[0][i] = v;
    }
}

// ---------------- GEMM: g_xc[m][n] = A[m][:K] @ W[K][2048] + bias[n] ----------------
// M=16384 rows (m = t*B + b). permute=1: A is inputs laid out [b][t][K].
// a_sel=1: A = g_hseq (device symbol). BM=64, BN=128, BK=16, 256 thr, 8x4 microtile.
__global__ void __launch_bounds__(256) gemm_bias(const float* __restrict__ A,
                                                 const float* __restrict__ W,
                                                 const float* __restrict__ bias,
                                                 int K, int permute, int a_sel) {
    __shared__ float As[64][16];
    __shared__ float Bs[16][128];
    const float* Ap = a_sel ? (const float*)g_hseq : A;
    const int tid = threadIdx.x;
    const int bm = blockIdx.y, bn = blockIdx.x;
    const int tr = tid >> 5, tc = tid & 31;

    float acc[8][4];
#pragma unroll
    for (int i = 0; i < 8; i++)
#pragma unroll
        for (int j = 0; j < 4; j++) acc[i][j] = 0.f;

    const int lr = tid >> 2;          // A-load row 0..63
    const int lq = (tid & 3) << 2;    // A-load col4
    const int br = tid >> 5;          // B-load row 0..7
    const int bc = (tid & 31) << 2;   // B-load col4
    const int rowg = bm * 64 + lr;
    const size_t abase = permute ? ((size_t)(rowg & 63) * T_ + (rowg >> 6)) * K
                                 : (size_t)rowg * K;

    for (int kt = 0; kt < K; kt += 16) {
        *(float4*)&As[lr][lq]  = *(const float4*)(Ap + abase + kt + lq);
        *(float4*)&Bs[br][bc]     = *(const float4*)(W + (size_t)(kt + br)     * G_ + bn * 128 + bc);
        *(float4*)&Bs[br + 8][bc] = *(const float4*)(W + (size_t)(kt + br + 8) * G_ + bn * 128 + bc);
        __syncthreads();
#pragma unroll
        for (int kk = 0; kk < 16; kk++) {
            float b[4], a[8];
#pragma unroll
            for (int j = 0; j < 4; j++) b[j] = Bs[kk][tc + 32 * j];
#pragma unroll
            for (int i = 0; i < 8; i++) a[i] = As[tr + 8 * i][kk];
#pragma unroll
            for (int i = 0; i < 8; i++)
#pragma unroll
                for (int j = 0; j < 4; j++) acc[i][j] += a[i] * b[j];
        }
        __syncthreads();
    }
#pragma unroll
    for (int i = 0; i < 8; i++) {
        int row = bm * 64 + tr + 8 * i;
#pragma unroll
        for (int j = 0; j < 4; j++) {
            int col = bn * 128 + tc + 32 * j;
            g_xc[(size_t)row * G_ + col] = acc[i][j] + bias[col];
        }
    }
}

// ---------------- persistent LSTM recurrence ----------------
// NCTA CTAs x 256 thr. CTA owns 4 units (16 gate cols: c = gate*4 + uu).
// Wh points at the h-rows of the layer weight ([U][4U], row stride G_).
// Compute role: ks = tid>>6 (K-split of 4x128), bg = (tid&63)>>2, cg = tid&3.
// Elementwise role: be = tid>>2 (batch), uu = tid&3 (unit). c-state in register.
#define REC_SMEM_FLOATS (64*516 + 512*16 + 4*64*16)
__global__ void __launch_bounds__(256) lstm_rec(const float* __restrict__ Wh,
                                                int init_slot, int save_slot) {
    extern __shared__ float sm[];
    float* h_sh = sm;                   // [64][516] padded
    float* W_sh = sm + 64 * 516;        // [512][16]
    float* part = W_sh + 512 * 16;      // [4][64][16]

    const int tid = threadIdx.x;
    const int u0 = blockIdx.x * 4;

    // load Wh slice: W_sh[k][c] with global col = (c/4)*512 + u0 + (c%4)
    for (int e = tid; e < 512 * 16; e += 256) {
        int k = e >> 4, c = e & 15;
        int gcol = (c >> 2) * 512 + u0 + (c & 3);
        W_sh[e] = Wh[(size_t)k * G_ + gcol];
    }

    const int ks = tid >> 6;
    const int rem = tid & 63;
    const int bg = rem >> 2;
    const int cg = rem & 3;
    const int k0 = ks * 128;

    const int be = tid >> 2, uu = tid & 3, u = u0 + uu;
    float cst = (init_slot >= 0) ? g_cst_s[init_slot][be * U_ + u] : 0.f;
    __syncthreads();

    int ph = 0;
    for (int t = 0; t < T_; t++) {
        // prefetch x-contrib gates (independent of h; latency hidden behind compute)
        const size_t xb = ((size_t)t * B_ + be) * G_ + u;
        float xg0 = g_xc[xb];
        float xg1 = g_xc[xb + 512];
        float xg2 = g_xc[xb + 1024];
        float xg3 = g_xc[xb + 1536];

        // broadcast h into smem (padded rows of 516 for conflict-free reads)
        const float4* hp = (const float4*)g_hbuf[ph];
#pragma unroll
        for (int i = 0; i < 32; i++) {
            int e = tid + i * 256;
            int b = e >> 7;
            int k4 = (e & 127) << 2;
            *(float4*)(h_sh + b * 516 + k4) = hp[e];
        }
        __syncthreads();

        float acc[4][4];
#pragma unroll
        for (int i = 0; i < 4; i++)
#pragma unroll
            for (int j = 0; j < 4; j++) acc[i][j] = 0.f;

        for (int kt = 0; kt < 128; kt += 8) {
#pragma unroll
            for (int kk = 0; kk < 8; kk++) {
                int k = k0 + kt + kk;
                float w0 = W_sh[k * 16 + cg * 4 + 0];
                float w1 = W_sh[k * 16 + cg * 4 + 1];
                float w2 = W_sh[k * 16 + cg * 4 + 2];
                float w3 = W_sh[k * 16 + cg * 4 + 3];
#pragma unroll
                for (int i = 0; i < 4; i++) {
                    float hv = h_sh[(bg + 16 * i) * 516 + k];
                    acc[i][0] += hv * w0;
                    acc[i][1] += hv * w1;
                    acc[i][2] += hv * w2;
                    acc[i][3] += hv * w3;
                }
            }
        }
#pragma unroll
        for (int i = 0; i < 4; i++)
#pragma unroll
            for (int j = 0; j < 4; j++)
                part[ks * 1024 + (bg + 16 * i) * 16 + cg * 4 + j] = acc[i][j];
        __syncthreads();

        // elementwise LSTM update for (be, uu)
        int p = be * 16 + uu;
        float gi = xg0 + part[p]          + part[1024 + p]          + part[2048 + p]          + part[3072 + p];
        float gj = xg1 + part[p + 4]      + part[1024 + p + 4]      + part[2048 + p + 4]      + part[3072 + p + 4];
        float gf = xg2 + part[p + 8]      + part[1024 + p + 8]      + part[2048 + p + 8]      + part[3072 + p + 8];
        float go = xg3 + part[p + 12]     + part[1024 + p + 12]     + part[2048 + p + 12]     + part[3072 + p + 12];

        cst = sigf(gf + 1.0f) * cst + sigf(gi) * tanhf(gj);
        float h = sigf(go) * tanhf(cst);

        g_hbuf[ph ^ 1][be * U_ + u] = h;
        g_hseq[((size_t)t * B_ + be) * U_ + u] = h;
        if (t == T_ - 1 && save_slot >= 0) {
            g_cst_s[save_slot][be * U_ + u] = cst;
            g_hst_s[save_slot][be * U_ + u] = h;
        }
        grid_bar();
        ph ^= 1;
    }
}

// ---------------- projection + mask: out[b][t][f] = (t < len[b]) ? hseq[t][b]·W[:,f] + b[f] : 0
#define PROJ_SMEM_FLOATS (512*64 + 512 + 256)
__global__ void __launch_bounds__(256) proj_kernel(const float* __restrict__ outW,
                                                   const float* __restrict__ outb,
                                                   const int* __restrict__ lens,
                                                   float* __restrict__ out) {
    extern __shared__ float ps[];
    float* Wsh = ps;                 // [512][64]
    float* hsh = Wsh + 512 * 64;     // [512]
    float* pp  = hsh + 512;          // [256]
    const int tid = threadIdx.x;
    for (int e = tid; e < 512 * 64; e += 256) Wsh[e] = outW[e];
    __syncthreads();
    const int f = tid & 63, ks = tid >> 6;
    for (int rr = 0; rr < 64; rr++) {
        int m = blockIdx.x * 64 + rr;
        if (tid < 128) ((float4*)hsh)[tid] = ((const float4*)(g_hseq + (size_t)m * U_))[tid];
        __syncthreads();
        float s = 0.f;
#pragma unroll 8
        for (int kk = 0; kk < 128; kk++) {
            int k = ks * 128 + kk;
            s += hsh[k] * Wsh[k * 64 + f];
        }
        pp[tid] = s;
        __syncthreads();
        if (tid < 64) {
            float v = pp[tid] + pp[64 + tid] + pp[128 + tid] + pp[192 + tid] + outb[tid];
            int t = m >> 6, b = m & 63;
            out[((size_t)b * T_ + t) * F_ + tid] = (t < lens[b]) ? v : 0.f;
        }
        __syncthreads();
    }
}

// ---------------- launch ----------------
extern "C" void kernel_launch(void* const* d_in, const int* in_sizes, int n_in,
                              void* d_out, int out_size) {
    const float* inputs  = (const float*)d_in[0];
    const float* targets = (const float*)d_in[1];
    const int*   lens    = (const int*)  d_in[2];
    const float* enc_W0  = (const float*)d_in[3];
    const float* enc_b0  = (const float*)d_in[4];
    const float* enc_W1  = (const float*)d_in[5];
    const float* enc_b1  = (const float*)d_in[6];
    const float* dec_W0  = (const float*)d_in[7];
    const float* dec_b0  = (const float*)d_in[8];
    const float* dec_W1  = (const float*)d_in[9];
    const float* dec_b1  = (const float*)d_in[10];
    const float* out_W   = (const float*)d_in[11];
    const float* out_b   = (const float*)d_in[12];

    const int REC_SMEM = REC_SMEM_FLOATS * 4;
    const int PROJ_SMEM = PROJ_SMEM_FLOATS * 4;
    cudaFuncSetAttribute(lstm_rec, cudaFuncAttributeMaxDynamicSharedMemorySize, REC_SMEM);
    cudaFuncSetAttribute(proj_kernel, cudaFuncAttributeMaxDynamicSharedMemorySize, PROJ_SMEM);

    dim3 ggrid(16, 256);  // N/128, M/64

    // ---- encoder layer 0
    set_h<<<NCTA, 256>>>(0);
    gemm_bias<<<ggrid, 256>>>(inputs, enc_W0, enc_b0, F_, 1, 0);
    lstm_rec<<<NCTA, 256, REC_SMEM>>>(enc_W0 + (size_t)F_ * G_, -1, 0);
    // ---- encoder layer 1
    gemm_bias<<<ggrid, 256>>>(nullptr, enc_W1, enc_b1, U_, 0, 1);
    set_h<<<NCTA, 256>>>(0);
    lstm_rec<<<NCTA, 256, REC_SMEM>>>(enc_W1 + (size_t)U_ * G_, -1, 1);
    // ---- decoder layer 0 (init = enc L0 finals)
    gemm_bias<<<ggrid, 256>>>(targets, dec_W0, dec_b0, F_, 1, 0);
    set_h<<<NCTA, 256>>>(1);
    lstm_rec<<<NCTA, 256, REC_SMEM>>>(dec_W0 + (size_t)F_ * G_, 0, -1);
    // ---- decoder layer 1 (init = enc L1 finals)
    gemm_bias<<<ggrid, 256>>>(nullptr, dec_W1, dec_b1, U_, 0, 1);
    set_h<<<NCTA, 256>>>(2);
    lstm_rec<<<NCTA, 256, REC_SMEM>>>(dec_W1 + (size_t)U_ * G_, 1, -1);
    // ---- projection + mask
    proj_kernel<<<256, 256, PROJ_SMEM>>>(out_W, out_b, lens, (float*)d_out);
}